// round 11
// baseline (speedup 1.0000x reference)
#include <cuda_runtime.h>
#include <cuda_bf16.h>
#include <math.h>
#include <cstdint>
#include <cstddef>

// ---------------- problem constants ----------------
#define S    2048
#define Hh   4096
#define NH   32
#define DN   128
#define DR   64
#define DV   128
#define QKD  192          // DN + DR
#define RQ   1536
#define RKV  512
#define CKVW 576          // RKV + DR
#define W1N  (RQ + CKVW)  // 2112: merged q_a + kv_a output width

#define SM_SCALE 0.072168783648703220563f   // 192^-0.5

// ---- big GEMM tiling ----
#define BM 128
#define BN 256
#define BK 16
#define LDT 20
#define STG 4
#define GTH 512                   // threads per GEMM CTA (16 warps)
#define AS_SZ (BM * LDT)          // 2560 floats
#define BS_SZ (BN * LDT)          // 5120 floats
#define GEMM_SMEM (STG * (AS_SZ + BS_SZ) * 4)   // 122880 B

// ---------------- scratch (device globals; allocation-free) ----------------
__device__ float g_qackv[S * W1N];          // [q_a | ckv] merged, tf32 values
__device__ float g_qan [S * RQ];
__device__ float g_q   [S * NH * QKD];
__device__ float g_ckvn[S * RKV];
__device__ float g_kv  [S * NH * (DN+DV)];
__device__ float g_Q   [(size_t)NH * S * QKD];
__device__ float g_K   [(size_t)NH * S * QKD];
__device__ float g_V   [(size_t)NH * S * DV];
__device__ float g_attn[S * Hh];
// tf32-pre-rounded copies of inputs (weights + hidden)
__device__ float g_hid [S * Hh];
__device__ float g_w1  [(size_t)W1N * Hh];  // [q_a_w ; kv_a_w] stacked along N
__device__ float g_qbw [NH * QKD * RQ];
__device__ float g_kvbw[NH * (DN+DV) * RKV];
__device__ float g_ow  [(size_t)Hh * Hh];

// ---------------- cp.async helpers ----------------
__device__ __forceinline__ void cp_async16(void* smem, const void* gmem, bool pred) {
    unsigned int s = (unsigned int)__cvta_generic_to_shared(smem);
    int sz = pred ? 16 : 0;
    asm volatile("cp.async.cg.shared.global [%0], [%1], 16, %2;\n" :: "r"(s), "l"(gmem), "r"(sz));
}
__device__ __forceinline__ void cp_async_commit() { asm volatile("cp.async.commit_group;\n"); }
template<int N_> __device__ __forceinline__ void cp_async_wait() { asm volatile("cp.async.wait_group %0;\n" :: "n"(N_)); }

// ---------------- tf32 helpers ----------------
__device__ __forceinline__ uint32_t f2tf(float x) {
    uint32_t r; asm("cvt.rna.tf32.f32 %0, %1;" : "=r"(r) : "f"(x)); return r;
}
__device__ __forceinline__ float tf32r(float x) { return __uint_as_float(f2tf(x)); }
__device__ __forceinline__ void mma_tf32(float* c, const uint32_t* a, uint32_t b0, uint32_t b1) {
    asm("mma.sync.aligned.m16n8k8.row.col.f32.tf32.tf32.f32 "
        "{%0,%1,%2,%3},{%4,%5,%6,%7},{%8,%9},{%0,%1,%2,%3};"
        : "+f"(c[0]), "+f"(c[1]), "+f"(c[2]), "+f"(c[3])
        : "r"(a[0]), "r"(a[1]), "r"(a[2]), "r"(a[3]), "r"(b0), "r"(b1));
}

// ---------------- elementwise tf32 rounding (float4 vectorized) ----------------
__global__ void round_tf32_kernel(const float4* __restrict__ in, float4* __restrict__ out, int n4) {
    int i = blockIdx.x * blockDim.x + threadIdx.x;
    if (i < n4) {
        float4 v = in[i];
        v.x = tf32r(v.x); v.y = tf32r(v.y); v.z = tf32r(v.z); v.w = tf32r(v.w);
        out[i] = v;
    }
}

// ============ big NT GEMM: C[M,N] = A[M,K] * B[N,K]^T (raw mma, tf32-in) ============
// 128x256 block tile, BK=16, 4-stage cp.async, 16 warps in 2(M)x8(N), warp tile 64x32.
__global__ __launch_bounds__(GTH, 1)
void gemm_nt_big(const float* __restrict__ A, const float* __restrict__ B,
                 float* __restrict__ C, int M, int N, int K) {
    extern __shared__ float smx[];
    const int tid  = threadIdx.x;
    const int warp = tid >> 5, lane = tid & 31;
    const int g    = lane >> 2, t = lane & 3;
    const int wm   = warp >> 3, wn = warp & 7;
    const int bm   = blockIdx.y * BM, bn = blockIdx.x * BN;

    float c[4][4][4];
#pragma unroll
    for (int i = 0; i < 4; i++)
#pragma unroll
        for (int j = 0; j < 4; j++) { c[i][j][0] = c[i][j][1] = c[i][j][2] = c[i][j][3] = 0.f; }

    const int T = K / BK;

    auto load_stage = [&](int kt, int stg) {
        float* As = smx + stg * (AS_SZ + BS_SZ);
        float* Bs = As + AS_SZ;
        const int k0 = kt * BK;
        {                                       // A: 128x16 = 512 16B-chunks
            int row = tid >> 2, col = (tid & 3) * 4;
            cp_async16(&As[row * LDT + col], A + (size_t)(bm + row) * K + k0 + col, true);
        }
#pragma unroll
        for (int u = 0; u < 2; u++) {           // B: 256x16 = 1024 chunks
            int f = tid + u * GTH;
            int row = f >> 2, col = (f & 3) * 4;
            bool p = (bn + row) < N;
            cp_async16(&Bs[row * LDT + col],
                       B + (size_t)(p ? (bn + row) : 0) * K + k0 + col, p);
        }
        cp_async_commit();
    };

#pragma unroll
    for (int s = 0; s < STG - 1; s++) {
        if (s < T) load_stage(s, s); else cp_async_commit();
    }

    for (int kt = 0; kt < T; kt++) {
        cp_async_wait<STG - 2>();
        __syncthreads();
        if (kt + STG - 1 < T) load_stage(kt + STG - 1, (kt + STG - 1) % STG);
        else cp_async_commit();                // keep group count consistent

        const float* As = smx + (kt % STG) * (AS_SZ + BS_SZ);
        const float* Bs = As + AS_SZ;
#pragma unroll
        for (int kk = 0; kk < BK; kk += 8) {
            uint32_t a[4][4];
#pragma unroll
            for (int i = 0; i < 4; i++) {
                const int rb = wm * 64 + i * 16;
                a[i][0] = __float_as_uint(As[(rb + g) * LDT + kk + t]);
                a[i][1] = __float_as_uint(As[(rb + g + 8) * LDT + kk + t]);
                a[i][2] = __float_as_uint(As[(rb + g) * LDT + kk + t + 4]);
                a[i][3] = __float_as_uint(As[(rb + g + 8) * LDT + kk + t + 4]);
            }
            uint32_t bf[4][2];
#pragma unroll
            for (int j = 0; j < 4; j++) {
                const int nb = wn * 32 + j * 8;
                bf[j][0] = __float_as_uint(Bs[(nb + g) * LDT + kk + t]);
                bf[j][1] = __float_as_uint(Bs[(nb + g) * LDT + kk + t + 4]);
            }
#pragma unroll
            for (int i = 0; i < 4; i++)
#pragma unroll
                for (int j = 0; j < 4; j++)
                    mma_tf32(c[i][j], a[i], bf[j][0], bf[j][1]);
        }
        __syncthreads();
    }

#pragma unroll
    for (int i = 0; i < 4; i++) {
        const int gm0 = bm + wm * 64 + i * 16 + g;
        const int gm1 = gm0 + 8;
#pragma unroll
        for (int j = 0; j < 4; j++) {
            const int gn = bn + wn * 32 + j * 8 + 2 * t;
            if (gn < N) {
                float2 v0; v0.x = c[i][j][0]; v0.y = c[i][j][1];
                float2 v1; v1.x = c[i][j][2]; v1.y = c[i][j][3];
                *(float2*)&C[(size_t)gm0 * N + gn] = v0;
                *(float2*)&C[(size_t)gm1 * N + gn] = v1;
            }
        }
    }
}

// ================== fused flash attention (tf32 mma.sync) ==================
#define KS_LD 196
#define VS_LD 136
#define PS_LD 68
#define KS_SZ (64 * KS_LD)
#define VS_SZ (64 * VS_LD)
#define PS_SZ (16 * PS_LD)
#define FLASH_SMEM ((2 * KS_SZ + 2 * VS_SZ + 8 * PS_SZ) * 4)

__global__ __launch_bounds__(256, 1)
void flash_attn(const float* __restrict__ Qb, const float* __restrict__ Kb,
                const float* __restrict__ Vb, float* __restrict__ Out) {
    extern __shared__ float sm[];
    float* KsB = sm;
    float* VsB = sm + 2 * KS_SZ;
    float* PsB = sm + 2 * KS_SZ + 2 * VS_SZ;

    const int qt   = (int)(gridDim.x - 1 - blockIdx.x);  // heavy tiles first
    const int h    = blockIdx.y;
    const int bm   = qt * 128;
    const int tid  = threadIdx.x;
    const int warp = tid >> 5, lane = tid & 31;
    const int g    = lane >> 2, t = lane & 3;
    const int row0 = bm + warp * 16 + g;
    const int row1 = row0 + 8;

    const float* Qh = Qb + (size_t)h * S * QKD;
    const float* Kh = Kb + (size_t)h * S * QKD;
    const float* Vh = Vb + (size_t)h * S * DV;
    float* Pw = PsB + warp * PS_SZ;

    uint32_t qa[24][4];
    {
        const float* q0 = Qh + (size_t)row0 * QKD;
        const float* q1 = Qh + (size_t)row1 * QKD;
#pragma unroll
        for (int kg = 0; kg < 24; kg++) {
            qa[kg][0] = __float_as_uint(__ldg(q0 + 8 * kg + t));
            qa[kg][1] = __float_as_uint(__ldg(q1 + 8 * kg + t));
            qa[kg][2] = __float_as_uint(__ldg(q0 + 8 * kg + t + 4));
            qa[kg][3] = __float_as_uint(__ldg(q1 + 8 * kg + t + 4));
        }
    }

    float o[16][4];
#pragma unroll
    for (int i = 0; i < 16; i++) { o[i][0] = o[i][1] = o[i][2] = o[i][3] = 0.f; }
    float m0 = -1e30f, m1 = -1e30f, l0 = 0.f, l1 = 0.f;

    const int NT = 2 * qt + 2;

    auto load_kv = [&](int jtile, int buf) {
        const float* ksrc = Kh + (size_t)(64 * jtile) * QKD;
        float* kdst = KsB + buf * KS_SZ;
#pragma unroll
        for (int i = 0; i < 12; i++) {
            int c = tid + i * 256;
            int r = c / 48, col = (c % 48) * 4;
            cp_async16(kdst + r * KS_LD + col, ksrc + (size_t)r * QKD + col, true);
        }
        const float* vsrc = Vh + (size_t)(64 * jtile) * DV;
        float* vdst = VsB + buf * VS_SZ;
#pragma unroll
        for (int i = 0; i < 8; i++) {
            int c = tid + i * 256;
            int r = c >> 5, col = (c & 31) * 4;
            cp_async16(vdst + r * VS_LD + col, vsrc + (size_t)r * DV + col, true);
        }
    };

    load_kv(0, 0);
    cp_async_commit();

    for (int jt = 0; jt < NT; jt++) {
        const int buf = jt & 1;
        __syncthreads();
        if (jt + 1 < NT) { load_kv(jt + 1, buf ^ 1); cp_async_commit(); cp_async_wait<1>(); }
        else             { cp_async_wait<0>(); }
        __syncthreads();

        const float* Kst = KsB + buf * KS_SZ;
        const float* Vst = VsB + buf * VS_SZ;

        float sc[8][4];
#pragma unroll
        for (int njp = 0; njp < 4; njp++) {
            float s0[4] = {0.f, 0.f, 0.f, 0.f};
            float s1[4] = {0.f, 0.f, 0.f, 0.f};
            const float* kr0 = Kst + (size_t)((2 * njp) * 8 + g) * KS_LD;
            const float* kr1 = Kst + (size_t)((2 * njp + 1) * 8 + g) * KS_LD;
#pragma unroll
            for (int kg = 0; kg < 24; kg++) {
                uint32_t b0 = __float_as_uint(kr0[8 * kg + t]);
                uint32_t b1 = __float_as_uint(kr0[8 * kg + t + 4]);
                mma_tf32(s0, qa[kg], b0, b1);
                uint32_t b2 = __float_as_uint(kr1[8 * kg + t]);
                uint32_t b3 = __float_as_uint(kr1[8 * kg + t + 4]);
                mma_tf32(s1, qa[kg], b2, b3);
            }
#pragma unroll
            for (int e = 0; e < 4; e++) { sc[2 * njp][e] = s0[e]; sc[2 * njp + 1][e] = s1[e]; }
        }

#pragma unroll
        for (int nj = 0; nj < 8; nj++) {
            int colb = 64 * jt + 8 * nj + 2 * t;
            if (colb     > row0) sc[nj][0] = -1e30f;
            if (colb + 1 > row0) sc[nj][1] = -1e30f;
            if (colb     > row1) sc[nj][2] = -1e30f;
            if (colb + 1 > row1) sc[nj][3] = -1e30f;
        }

        float tm0 = -1e30f, tm1 = -1e30f;
#pragma unroll
        for (int nj = 0; nj < 8; nj++) {
            tm0 = fmaxf(tm0, fmaxf(sc[nj][0], sc[nj][1]));
            tm1 = fmaxf(tm1, fmaxf(sc[nj][2], sc[nj][3]));
        }
        tm0 = fmaxf(tm0, __shfl_xor_sync(0xffffffffu, tm0, 1));
        tm0 = fmaxf(tm0, __shfl_xor_sync(0xffffffffu, tm0, 2));
        tm1 = fmaxf(tm1, __shfl_xor_sync(0xffffffffu, tm1, 1));
        tm1 = fmaxf(tm1, __shfl_xor_sync(0xffffffffu, tm1, 2));
        const float nm0 = fmaxf(m0, tm0), nm1 = fmaxf(m1, tm1);
        const float al0 = expf((m0 - nm0) * SM_SCALE);
        const float al1 = expf((m1 - nm1) * SM_SCALE);

        float rs0 = 0.f, rs1 = 0.f;
#pragma unroll
        for (int nj = 0; nj < 8; nj++) {
            float p0 = expf((sc[nj][0] - nm0) * SM_SCALE);
            float p1 = expf((sc[nj][1] - nm0) * SM_SCALE);
            float p2 = expf((sc[nj][2] - nm1) * SM_SCALE);
            float p3 = expf((sc[nj][3] - nm1) * SM_SCALE);
            rs0 += p0 + p1;
            rs1 += p2 + p3;
            uint2 u01; u01.x = f2tf(p0); u01.y = f2tf(p1);
            uint2 u23; u23.x = f2tf(p2); u23.y = f2tf(p3);
            *(uint2*)(Pw + g * PS_LD + 8 * nj + 2 * t)       = u01;
            *(uint2*)(Pw + (g + 8) * PS_LD + 8 * nj + 2 * t) = u23;
        }
        l0 = l0 * al0 + rs0;
        l1 = l1 * al1 + rs1;
        m0 = nm0; m1 = nm1;
#pragma unroll
        for (int dj = 0; dj < 16; dj++) {
            o[dj][0] *= al0; o[dj][1] *= al0;
            o[dj][2] *= al1; o[dj][3] *= al1;
        }
        __syncwarp();

#pragma unroll
        for (int kg = 0; kg < 8; kg++) {
            uint32_t pa[4];
            pa[0] = __float_as_uint(Pw[g * PS_LD + 8 * kg + t]);
            pa[1] = __float_as_uint(Pw[(g + 8) * PS_LD + 8 * kg + t]);
            pa[2] = __float_as_uint(Pw[g * PS_LD + 8 * kg + t + 4]);
            pa[3] = __float_as_uint(Pw[(g + 8) * PS_LD + 8 * kg + t + 4]);
            const float* v0 = Vst + (size_t)(8 * kg + t) * VS_LD;
            const float* v1 = Vst + (size_t)(8 * kg + t + 4) * VS_LD;
#pragma unroll
            for (int dj = 0; dj < 16; dj += 2) {
                uint32_t b0 = __float_as_uint(v0[8 * dj + g]);
                uint32_t b1 = __float_as_uint(v1[8 * dj + g]);
                mma_tf32(o[dj], pa, b0, b1);
                uint32_t b2 = __float_as_uint(v0[8 * (dj + 1) + g]);
                uint32_t b3 = __float_as_uint(v1[8 * (dj + 1) + g]);
                mma_tf32(o[dj + 1], pa, b2, b3);
            }
        }
        __syncwarp();
    }

    // quad reduction of softmax denominator
    l0 += __shfl_xor_sync(0xffffffffu, l0, 1);
    l0 += __shfl_xor_sync(0xffffffffu, l0, 2);
    l1 += __shfl_xor_sync(0xffffffffu, l1, 1);
    l1 += __shfl_xor_sync(0xffffffffu, l1, 2);

    const float inv0 = 1.f / l0, inv1 = 1.f / l1;
    float* or0 = Out + (size_t)row0 * Hh + h * DV;
    float* or1 = Out + (size_t)row1 * Hh + h * DV;
#pragma unroll
    for (int dj = 0; dj < 16; dj++) {
        float2 w0; w0.x = tf32r(o[dj][0] * inv0); w0.y = tf32r(o[dj][1] * inv0);
        float2 w1; w1.x = tf32r(o[dj][2] * inv1); w1.y = tf32r(o[dj][3] * inv1);
        *(float2*)(or0 + 8 * dj + 2 * t) = w0;
        *(float2*)(or1 + 8 * dj + 2 * t) = w1;
    }
}

// ---------------- rmsnorm over first K cols; output tf32-rounded ----------------
__global__ void rmsnorm_kernel(const float* __restrict__ X, const float* __restrict__ w,
                               float* __restrict__ Y, int K, int ldx, int ldy) {
    const int row = blockIdx.x;
    const float* x = X + (size_t)row * ldx;
    float* y = Y + (size_t)row * ldy;
    float ss = 0.f;
    for (int j = threadIdx.x; j < K; j += blockDim.x) { float v = x[j]; ss += v * v; }
    __shared__ float red[256];
    red[threadIdx.x] = ss;
    __syncthreads();
    for (int s = 128; s > 0; s >>= 1) {
        if (threadIdx.x < s) red[threadIdx.x] += red[threadIdx.x + s];
        __syncthreads();
    }
    float inv = rsqrtf(red[0] / (float)K + 1e-6f);
    for (int j = threadIdx.x; j < K; j += blockDim.x) y[j] = tf32r(x[j] * inv * w[j]);
}

// ---------------- build Q: grid S, 256 threads; cos/sin computed once ----------------
__global__ void build_q2(const float* __restrict__ q, const float* __restrict__ freqs,
                         float* __restrict__ Qb) {
    const int s = blockIdx.x;
    __shared__ float cs[DR];          // [cos(0..31) | sin(0..31)]
    if (threadIdx.x < DR / 2) {
        float f = freqs[s * (DR / 2) + threadIdx.x];
        cs[threadIdx.x]      = cosf(f);
        cs[32 + threadIdx.x] = sinf(f);
    }
    __syncthreads();
    const float* qs = q + (size_t)s * (NH * QKD);
    for (int idx = threadIdx.x; idx < NH * QKD; idx += 256) {
        int h = idx / QKD, d = idx - h * QKD;
        float val;
        if (d < DN) {
            val = qs[h * QKD + d];
        } else {
            int u = d - DN, t = u >> 1;
            float c = cs[t], sn = cs[32 + t];
            float xr = qs[h * QKD + DN + 2 * t], xi = qs[h * QKD + DN + 2 * t + 1];
            val = (u & 1) ? (xr * sn + xi * c) : (xr * c - xi * sn);
        }
        Qb[((size_t)h * S + s) * QKD + d] = tf32r(val);
    }
}

// ---------------- build K/V: rot part computed once (shared across heads) ----------------
__global__ void build_kv2(const float* __restrict__ kv, const float* __restrict__ qackv,
                          const float* __restrict__ freqs,
                          float* __restrict__ Kb, float* __restrict__ Vb) {
    const int s = blockIdx.x;
    __shared__ float rot[DR];
    if (threadIdx.x < DR / 2) {
        float f = freqs[s * (DR / 2) + threadIdx.x];
        float c = cosf(f), sn = sinf(f);
        const float* kr = qackv + (size_t)s * W1N + (RQ + RKV);
        float xr = kr[2 * threadIdx.x], xi = kr[2 * threadIdx.x + 1];
        rot[2 * threadIdx.x]     = tf32r(xr * c - xi * sn);
        rot[2 * threadIdx.x + 1] = tf32r(xr * sn + xi * c);
    }
    __syncthreads();
    const float* kvs = kv + (size_t)s * (NH * (DN + DV));
    const int PER = DN + DV + DR;    // 320 outputs per head
    for (int idx = threadIdx.x; idx < NH * PER; idx += 256) {
        int h = idx / PER, d = idx - h * PER;
        if (d < DN) {
            Kb[((size_t)h * S + s) * QKD + d] = tf32r(kvs[h * (DN + DV) + d]);
        } else if (d < QKD) {
            Kb[((size_t)h * S + s) * QKD + d] = rot[d - DN];
        } else {
            int dv = d - QKD;
            Vb[((size_t)h * S + s) * DV + dv] = tf32r(kvs[h * (DN + DV) + DN + dv]);
        }
    }
}

// ---------------- host ----------------
static float* sym_addr(const void* symbol) {
    void* p = nullptr;
    cudaGetSymbolAddress(&p, symbol);
    return (float*)p;
}

static void launch_round(const float* src, float* dst, size_t n) {
    int n4 = (int)(n / 4);
    round_tf32_kernel<<<(n4 + 255) / 256, 256>>>((const float4*)src, (float4*)dst, n4);
}

static void launch_gemm(const float* A, const float* B, float* C, int M, int N, int K) {
    dim3 grid((N + BN - 1) / BN, M / BM);
    gemm_nt_big<<<grid, GTH, GEMM_SMEM>>>(A, B, C, M, N, K);
}

extern "C" void kernel_launch(void* const* d_in, const int* in_sizes, int n_in,
                              void* d_out, int out_size) {
    const float* hidden    = (const float*)d_in[0];
    const float* freqs     = (const float*)d_in[1];
    const float* q_a_w     = (const float*)d_in[2];
    const float* q_a_ln_w  = (const float*)d_in[3];
    const float* q_b_w     = (const float*)d_in[4];
    const float* kv_a_w    = (const float*)d_in[5];
    const float* kv_a_ln_w = (const float*)d_in[6];
    const float* kv_b_w    = (const float*)d_in[7];
    const float* o_w       = (const float*)d_in[8];
    float* out = (float*)d_out;

    float* qackv = sym_addr(g_qackv);
    float* qan  = sym_addr(g_qan);
    float* q    = sym_addr(g_q);
    float* ckvn = sym_addr(g_ckvn);
    float* kv   = sym_addr(g_kv);
    float* Qb   = sym_addr(g_Q);
    float* Kb   = sym_addr(g_K);
    float* Vb   = sym_addr(g_V);
    float* attn = sym_addr(g_attn);
    float* hid  = sym_addr(g_hid);
    float* w1   = sym_addr(g_w1);
    float* qbw  = sym_addr(g_qbw);
    float* kvbw = sym_addr(g_kvbw);
    float* ow   = sym_addr(g_ow);

    cudaFuncSetAttribute(flash_attn, cudaFuncAttributeMaxDynamicSharedMemorySize, FLASH_SMEM);
    cudaFuncSetAttribute(gemm_nt_big, cudaFuncAttributeMaxDynamicSharedMemorySize, GEMM_SMEM);

    // 0) pre-round inputs to tf32 (rna), once per call
    launch_round(hidden, hid,  (size_t)S * Hh);
    launch_round(q_a_w,  w1,                    (size_t)RQ * Hh);    // rows 0..1535
    launch_round(kv_a_w, w1 + (size_t)RQ * Hh,  (size_t)CKVW * Hh);  // rows 1536..2111
    launch_round(q_b_w,  qbw,  (size_t)NH * QKD * RQ);
    launch_round(kv_b_w, kvbw, (size_t)NH * (DN + DV) * RKV);
    launch_round(o_w,    ow,   (size_t)Hh * Hh);

    // 1) [q_a | ckv] = hid @ w1^T   [2048, 2112]  (merged G1+G4, one full wave)
    launch_gemm(hid, w1, qackv, S, W1N, Hh);
    // 2) rmsnorm(q_a) -> tf32
    rmsnorm_kernel<<<S, 256>>>(qackv, q_a_ln_w, qan, RQ, W1N, RQ);
    // 3) q = qan @ qbw^T            [2048,6144]
    launch_gemm(qan, qbw, q, S, NH * QKD, RQ);
    // 5) rmsnorm(ckv[:, :512]) -> tf32
    rmsnorm_kernel<<<S, 256>>>(qackv + RQ, kv_a_ln_w, ckvn, RKV, W1N, RKV);
    // 6) kv = ckvn @ kvbw^T         [2048,8192]
    launch_gemm(ckvn, kvbw, kv, S, NH * (DN + DV), RKV);
    // 7) assemble Q with RoPE (tf32)
    build_q2<<<S, 256>>>(q, freqs, Qb);
    // 8) assemble K (RoPE, shared rot) and V (tf32)
    build_kv2<<<S, 256>>>(kv, qackv, freqs, Kb, Vb);
    // 9-11) fused flash attention -> g_attn (tf32-rounded)
    flash_attn<<<dim3(S / 128, NH), 256, FLASH_SMEM>>>(Qb, Kb, Vb, attn);
    // 12) out = attn @ ow^T         [2048,4096]
    launch_gemm(attn, ow, out, S, Hh, Hh);
}

// round 12
// speedup vs baseline: 1.1573x; 1.1573x over previous
#include <cuda_runtime.h>
#include <cuda_bf16.h>
#include <math.h>
#include <cstdint>
#include <cstddef>

// ---------------- problem constants ----------------
#define S    2048
#define Hh   4096
#define NH   32
#define DN   128
#define DR   64
#define DV   128
#define QKD  192          // DN + DR
#define RQ   1536
#define RKV  512
#define CKVW 576          // RKV + DR
#define W1N  (RQ + CKVW)  // 2112: merged q_a + kv_a output width

#define SM_SCALE 0.072168783648703220563f   // 192^-0.5

// ---- big GEMM tiling ----
#define BM 128
#define BN 256
#define BK 16
#define LDT 24            // floats; LDT/2=12 ≡ 12 mod 16 -> conflict-free LDS.64
#define STG 4
#define AS_SZ (BM * LDT)          // 3072 floats
#define BS_SZ (BN * LDT)          // 6144 floats
#define GEMM_SMEM (STG * (AS_SZ + BS_SZ) * 4)   // 147456 B

// ---------------- scratch (device globals; allocation-free) ----------------
__device__ float g_qackv[S * W1N];          // [q_a | ckv] merged, tf32 values
__device__ float g_qan [S * RQ];
__device__ float g_q   [S * NH * QKD];
__device__ float g_ckvn[S * RKV];
__device__ float g_kv  [S * NH * (DN+DV)];
__device__ float g_Q   [(size_t)NH * S * QKD];
__device__ float g_K   [(size_t)NH * S * QKD];
__device__ float g_V   [(size_t)NH * S * DV];
__device__ float g_attn[S * Hh];
// tf32-pre-rounded copies of inputs (weights + hidden)
__device__ float g_hid [S * Hh];
__device__ float g_w1  [(size_t)W1N * Hh];  // [q_a_w ; kv_a_w] stacked along N
__device__ float g_qbw [NH * QKD * RQ];
__device__ float g_kvbw[NH * (DN+DV) * RKV];
__device__ float g_ow  [(size_t)Hh * Hh];

// ---------------- cp.async helpers ----------------
__device__ __forceinline__ void cp_async16(void* smem, const void* gmem, bool pred) {
    unsigned int s = (unsigned int)__cvta_generic_to_shared(smem);
    int sz = pred ? 16 : 0;
    asm volatile("cp.async.cg.shared.global [%0], [%1], 16, %2;\n" :: "r"(s), "l"(gmem), "r"(sz));
}
__device__ __forceinline__ void cp_async_commit() { asm volatile("cp.async.commit_group;\n"); }
template<int N_> __device__ __forceinline__ void cp_async_wait() { asm volatile("cp.async.wait_group %0;\n" :: "n"(N_)); }

// ---------------- tf32 helpers ----------------
__device__ __forceinline__ uint32_t f2tf(float x) {
    uint32_t r; asm("cvt.rna.tf32.f32 %0, %1;" : "=r"(r) : "f"(x)); return r;
}
__device__ __forceinline__ float tf32r(float x) { return __uint_as_float(f2tf(x)); }
__device__ __forceinline__ void mma_tf32(float* c, const uint32_t* a, uint32_t b0, uint32_t b1) {
    asm("mma.sync.aligned.m16n8k8.row.col.f32.tf32.tf32.f32 "
        "{%0,%1,%2,%3},{%4,%5,%6,%7},{%8,%9},{%0,%1,%2,%3};"
        : "+f"(c[0]), "+f"(c[1]), "+f"(c[2]), "+f"(c[3])
        : "r"(a[0]), "r"(a[1]), "r"(a[2]), "r"(a[3]), "r"(b0), "r"(b1));
}

// ---------------- elementwise tf32 rounding (float4 vectorized) ----------------
__global__ void round_tf32_kernel(const float4* __restrict__ in, float4* __restrict__ out, int n4) {
    int i = blockIdx.x * blockDim.x + threadIdx.x;
    if (i < n4) {
        float4 v = in[i];
        v.x = tf32r(v.x); v.y = tf32r(v.y); v.z = tf32r(v.z); v.w = tf32r(v.w);
        out[i] = v;
    }
}

// ============ big NT GEMM: C[M,N] = A[M,K] * B[N,K]^T (raw mma, tf32-in) ============
// 128x256 block tile, BK=16, 4-stage cp.async, 8 warps in 2(M)x4(N), warp tile 64x64.
// k-permuted fragment slots: thread t holds k = {2t, 2t+1} -> LDS.64 fragment loads.
__global__ __launch_bounds__(256, 1)
void gemm_nt_big(const float* __restrict__ A, const float* __restrict__ B,
                 float* __restrict__ C, int M, int N, int K) {
    extern __shared__ float smx[];
    const int tid  = threadIdx.x;
    const int warp = tid >> 5, lane = tid & 31;
    const int g    = lane >> 2, t = lane & 3;
    const int wm   = warp >> 2, wn = warp & 3;
    const int bm   = blockIdx.y * BM, bn = blockIdx.x * BN;

    float c[4][8][4];
#pragma unroll
    for (int i = 0; i < 4; i++)
#pragma unroll
        for (int j = 0; j < 8; j++) { c[i][j][0] = c[i][j][1] = c[i][j][2] = c[i][j][3] = 0.f; }

    const int T = K / BK;

    auto load_stage = [&](int kt, int stg) {
        float* As = smx + stg * (AS_SZ + BS_SZ);
        float* Bs = As + AS_SZ;
        const int k0 = kt * BK;
#pragma unroll
        for (int u = 0; u < 2; u++) {          // A: 128x16 = 512 16B-chunks
            int f = tid + u * 256;
            int row = f >> 2, col = (f & 3) * 4;
            cp_async16(&As[row * LDT + col], A + (size_t)(bm + row) * K + k0 + col, true);
        }
#pragma unroll
        for (int u = 0; u < 4; u++) {          // B: 256x16 = 1024 chunks
            int f = tid + u * 256;
            int row = f >> 2, col = (f & 3) * 4;
            bool p = (bn + row) < N;
            cp_async16(&Bs[row * LDT + col],
                       B + (size_t)(p ? (bn + row) : 0) * K + k0 + col, p);
        }
        cp_async_commit();
    };

#pragma unroll
    for (int s = 0; s < STG - 1; s++) {
        if (s < T) load_stage(s, s); else cp_async_commit();
    }

    for (int kt = 0; kt < T; kt++) {
        cp_async_wait<STG - 2>();
        __syncthreads();
        if (kt + STG - 1 < T) load_stage(kt + STG - 1, (kt + STG - 1) % STG);
        else cp_async_commit();                // keep group count consistent

        const float* As = smx + (kt % STG) * (AS_SZ + BS_SZ);
        const float* Bs = As + AS_SZ;
        const float2* As2 = reinterpret_cast<const float2*>(As);
        const float2* Bs2 = reinterpret_cast<const float2*>(Bs);
#pragma unroll
        for (int kk = 0; kk < BK; kk += 8) {
            const int kb = kk >> 1;            // float2 offset within row
            uint32_t a[4][4];
#pragma unroll
            for (int i = 0; i < 4; i++) {
                const int rb = wm * 64 + i * 16;
                float2 v0 = As2[(rb + g) * (LDT / 2) + kb + t];       // k = 2t, 2t+1
                float2 v1 = As2[(rb + g + 8) * (LDT / 2) + kb + t];
                a[i][0] = __float_as_uint(v0.x);
                a[i][1] = __float_as_uint(v1.x);
                a[i][2] = __float_as_uint(v0.y);
                a[i][3] = __float_as_uint(v1.y);
            }
            uint32_t bf[8][2];
#pragma unroll
            for (int j = 0; j < 8; j++) {
                const int nb = wn * 64 + j * 8;
                float2 v = Bs2[(nb + g) * (LDT / 2) + kb + t];        // same k mapping
                bf[j][0] = __float_as_uint(v.x);
                bf[j][1] = __float_as_uint(v.y);
            }
#pragma unroll
            for (int i = 0; i < 4; i++)
#pragma unroll
                for (int j = 0; j < 8; j++)
                    mma_tf32(c[i][j], a[i], bf[j][0], bf[j][1]);
        }
        __syncthreads();
    }

#pragma unroll
    for (int i = 0; i < 4; i++) {
        const int gm0 = bm + wm * 64 + i * 16 + g;
        const int gm1 = gm0 + 8;
#pragma unroll
        for (int j = 0; j < 8; j++) {
            const int gn = bn + wn * 64 + j * 8 + 2 * t;
            if (gn < N) {
                float2 v0; v0.x = c[i][j][0]; v0.y = c[i][j][1];
                float2 v1; v1.x = c[i][j][2]; v1.y = c[i][j][3];
                *(float2*)&C[(size_t)gm0 * N + gn] = v0;
                *(float2*)&C[(size_t)gm1 * N + gn] = v1;
            }
        }
    }
}

// ================== fused flash attention (tf32 mma.sync) ==================
#define KS_LD 200          // floats; KS_LD/2=100 ≡ 4 mod 16 -> conflict-free LDS.64
#define VS_LD 136
#define PS_LD 68
#define KS_SZ (64 * KS_LD)
#define VS_SZ (64 * VS_LD)
#define PS_SZ (16 * PS_LD)
#define FLASH_SMEM ((2 * KS_SZ + 2 * VS_SZ + 8 * PS_SZ) * 4)

__global__ __launch_bounds__(256, 1)
void flash_attn(const float* __restrict__ Qb, const float* __restrict__ Kb,
                const float* __restrict__ Vb, float* __restrict__ Out) {
    extern __shared__ float sm[];
    float* KsB = sm;
    float* VsB = sm + 2 * KS_SZ;
    float* PsB = sm + 2 * KS_SZ + 2 * VS_SZ;

    const int qt   = (int)(gridDim.x - 1 - blockIdx.x);  // heavy tiles first
    const int h    = blockIdx.y;
    const int bm   = qt * 128;
    const int tid  = threadIdx.x;
    const int warp = tid >> 5, lane = tid & 31;
    const int g    = lane >> 2, t = lane & 3;
    const int row0 = bm + warp * 16 + g;
    const int row1 = row0 + 8;

    const float* Qh = Qb + (size_t)h * S * QKD;
    const float* Kh = Kb + (size_t)h * S * QKD;
    const float* Vh = Vb + (size_t)h * S * DV;
    float* Pw = PsB + warp * PS_SZ;

    // ---- preload Q fragments, k-permuted slots: k = {2t, 2t+1} ----
    uint32_t qa[24][4];
    {
        const float* q0 = Qh + (size_t)row0 * QKD;
        const float* q1 = Qh + (size_t)row1 * QKD;
#pragma unroll
        for (int kg = 0; kg < 24; kg++) {
            float2 w0 = *(const float2*)(q0 + 8 * kg + 2 * t);
            float2 w1 = *(const float2*)(q1 + 8 * kg + 2 * t);
            qa[kg][0] = __float_as_uint(w0.x);
            qa[kg][1] = __float_as_uint(w1.x);
            qa[kg][2] = __float_as_uint(w0.y);
            qa[kg][3] = __float_as_uint(w1.y);
        }
    }

    float o[16][4];
#pragma unroll
    for (int i = 0; i < 16; i++) { o[i][0] = o[i][1] = o[i][2] = o[i][3] = 0.f; }
    float m0 = -1e30f, m1 = -1e30f, l0 = 0.f, l1 = 0.f;

    const int NT = 2 * qt + 2;

    auto load_kv = [&](int jtile, int buf) {
        const float* ksrc = Kh + (size_t)(64 * jtile) * QKD;
        float* kdst = KsB + buf * KS_SZ;
#pragma unroll
        for (int i = 0; i < 12; i++) {
            int c = tid + i * 256;
            int r = c / 48, col = (c % 48) * 4;
            cp_async16(kdst + r * KS_LD + col, ksrc + (size_t)r * QKD + col, true);
        }
        const float* vsrc = Vh + (size_t)(64 * jtile) * DV;
        float* vdst = VsB + buf * VS_SZ;
#pragma unroll
        for (int i = 0; i < 8; i++) {
            int c = tid + i * 256;
            int r = c >> 5, col = (c & 31) * 4;
            cp_async16(vdst + r * VS_LD + col, vsrc + (size_t)r * DV + col, true);
        }
    };

    load_kv(0, 0);
    cp_async_commit();

    for (int jt = 0; jt < NT; jt++) {
        const int buf = jt & 1;
        __syncthreads();
        if (jt + 1 < NT) { load_kv(jt + 1, buf ^ 1); cp_async_commit(); cp_async_wait<1>(); }
        else             { cp_async_wait<0>(); }
        __syncthreads();

        const float* Kst = KsB + buf * KS_SZ;
        const float* Vst = VsB + buf * VS_SZ;

        // ---- S = Q K^T (16 x 64 per warp), float2 K fragment loads ----
        float sc[8][4];
#pragma unroll
        for (int njp = 0; njp < 4; njp++) {
            float s0[4] = {0.f, 0.f, 0.f, 0.f};
            float s1[4] = {0.f, 0.f, 0.f, 0.f};
            const float* kr0 = Kst + (size_t)((2 * njp) * 8 + g) * KS_LD;
            const float* kr1 = Kst + (size_t)((2 * njp + 1) * 8 + g) * KS_LD;
#pragma unroll
            for (int kg = 0; kg < 24; kg++) {
                float2 vb0 = *(const float2*)(kr0 + 8 * kg + 2 * t);
                mma_tf32(s0, qa[kg], __float_as_uint(vb0.x), __float_as_uint(vb0.y));
                float2 vb1 = *(const float2*)(kr1 + 8 * kg + 2 * t);
                mma_tf32(s1, qa[kg], __float_as_uint(vb1.x), __float_as_uint(vb1.y));
            }
#pragma unroll
            for (int e = 0; e < 4; e++) { sc[2 * njp][e] = s0[e]; sc[2 * njp + 1][e] = s1[e]; }
        }

        // ---- causal mask ----
#pragma unroll
        for (int nj = 0; nj < 8; nj++) {
            int colb = 64 * jt + 8 * nj + 2 * t;
            if (colb     > row0) sc[nj][0] = -1e30f;
            if (colb + 1 > row0) sc[nj][1] = -1e30f;
            if (colb     > row1) sc[nj][2] = -1e30f;
            if (colb + 1 > row1) sc[nj][3] = -1e30f;
        }

        // ---- online softmax (rows g and g+8) ----
        float tm0 = -1e30f, tm1 = -1e30f;
#pragma unroll
        for (int nj = 0; nj < 8; nj++) {
            tm0 = fmaxf(tm0, fmaxf(sc[nj][0], sc[nj][1]));
            tm1 = fmaxf(tm1, fmaxf(sc[nj][2], sc[nj][3]));
        }
        tm0 = fmaxf(tm0, __shfl_xor_sync(0xffffffffu, tm0, 1));
        tm0 = fmaxf(tm0, __shfl_xor_sync(0xffffffffu, tm0, 2));
        tm1 = fmaxf(tm1, __shfl_xor_sync(0xffffffffu, tm1, 1));
        tm1 = fmaxf(tm1, __shfl_xor_sync(0xffffffffu, tm1, 2));
        const float nm0 = fmaxf(m0, tm0), nm1 = fmaxf(m1, tm1);
        const float al0 = expf((m0 - nm0) * SM_SCALE);
        const float al1 = expf((m1 - nm1) * SM_SCALE);

        float rs0 = 0.f, rs1 = 0.f;
#pragma unroll
        for (int nj = 0; nj < 8; nj++) {
            float p0 = expf((sc[nj][0] - nm0) * SM_SCALE);
            float p1 = expf((sc[nj][1] - nm0) * SM_SCALE);
            float p2 = expf((sc[nj][2] - nm1) * SM_SCALE);
            float p3 = expf((sc[nj][3] - nm1) * SM_SCALE);
            rs0 += p0 + p1;
            rs1 += p2 + p3;
            uint2 u01; u01.x = f2tf(p0); u01.y = f2tf(p1);
            uint2 u23; u23.x = f2tf(p2); u23.y = f2tf(p3);
            *(uint2*)(Pw + g * PS_LD + 8 * nj + 2 * t)       = u01;
            *(uint2*)(Pw + (g + 8) * PS_LD + 8 * nj + 2 * t) = u23;
        }
        l0 = l0 * al0 + rs0;
        l1 = l1 * al1 + rs1;
        m0 = nm0; m1 = nm1;
#pragma unroll
        for (int dj = 0; dj < 16; dj++) {
            o[dj][0] *= al0; o[dj][1] *= al0;
            o[dj][2] *= al1; o[dj][3] *= al1;
        }
        __syncwarp();

        // ---- O += P V ----
#pragma unroll
        for (int kg = 0; kg < 8; kg++) {
            uint32_t pa[4];
            pa[0] = __float_as_uint(Pw[g * PS_LD + 8 * kg + t]);
            pa[1] = __float_as_uint(Pw[(g + 8) * PS_LD + 8 * kg + t]);
            pa[2] = __float_as_uint(Pw[g * PS_LD + 8 * kg + t + 4]);
            pa[3] = __float_as_uint(Pw[(g + 8) * PS_LD + 8 * kg + t + 4]);
            const float* v0 = Vst + (size_t)(8 * kg + t) * VS_LD;
            const float* v1 = Vst + (size_t)(8 * kg + t + 4) * VS_LD;
#pragma unroll
            for (int dj = 0; dj < 16; dj += 2) {
                uint32_t b0 = __float_as_uint(v0[8 * dj + g]);
                uint32_t b1 = __float_as_uint(v1[8 * dj + g]);
                mma_tf32(o[dj], pa, b0, b1);
                uint32_t b2 = __float_as_uint(v0[8 * (dj + 1) + g]);
                uint32_t b3 = __float_as_uint(v1[8 * (dj + 1) + g]);
                mma_tf32(o[dj + 1], pa, b2, b3);
            }
        }
        __syncwarp();
    }

    // quad reduction of softmax denominator
    l0 += __shfl_xor_sync(0xffffffffu, l0, 1);
    l0 += __shfl_xor_sync(0xffffffffu, l0, 2);
    l1 += __shfl_xor_sync(0xffffffffu, l1, 1);
    l1 += __shfl_xor_sync(0xffffffffu, l1, 2);

    const float inv0 = 1.f / l0, inv1 = 1.f / l1;
    float* or0 = Out + (size_t)row0 * Hh + h * DV;
    float* or1 = Out + (size_t)row1 * Hh + h * DV;
#pragma unroll
    for (int dj = 0; dj < 16; dj++) {
        float2 w0; w0.x = tf32r(o[dj][0] * inv0); w0.y = tf32r(o[dj][1] * inv0);
        float2 w1; w1.x = tf32r(o[dj][2] * inv1); w1.y = tf32r(o[dj][3] * inv1);
        *(float2*)(or0 + 8 * dj + 2 * t) = w0;
        *(float2*)(or1 + 8 * dj + 2 * t) = w1;
    }
}

// ---------------- rmsnorm over first K cols; output tf32-rounded ----------------
__global__ void rmsnorm_kernel(const float* __restrict__ X, const float* __restrict__ w,
                               float* __restrict__ Y, int K, int ldx, int ldy) {
    const int row = blockIdx.x;
    const float* x = X + (size_t)row * ldx;
    float* y = Y + (size_t)row * ldy;
    float ss = 0.f;
    for (int j = threadIdx.x; j < K; j += blockDim.x) { float v = x[j]; ss += v * v; }
    __shared__ float red[256];
    red[threadIdx.x] = ss;
    __syncthreads();
    for (int s = 128; s > 0; s >>= 1) {
        if (threadIdx.x < s) red[threadIdx.x] += red[threadIdx.x + s];
        __syncthreads();
    }
    float inv = rsqrtf(red[0] / (float)K + 1e-6f);
    for (int j = threadIdx.x; j < K; j += blockDim.x) y[j] = tf32r(x[j] * inv * w[j]);
}

// ---------------- build Q: grid S, 256 threads; cos/sin computed once ----------------
__global__ void build_q2(const float* __restrict__ q, const float* __restrict__ freqs,
                         float* __restrict__ Qb) {
    const int s = blockIdx.x;
    __shared__ float cs[DR];          // [cos(0..31) | sin(0..31)]
    if (threadIdx.x < DR / 2) {
        float f = freqs[s * (DR / 2) + threadIdx.x];
        cs[threadIdx.x]      = cosf(f);
        cs[32 + threadIdx.x] = sinf(f);
    }
    __syncthreads();
    const float* qs = q + (size_t)s * (NH * QKD);
    for (int idx = threadIdx.x; idx < NH * QKD; idx += 256) {
        int h = idx / QKD, d = idx - h * QKD;
        float val;
        if (d < DN) {
            val = qs[h * QKD + d];
        } else {
            int u = d - DN, t = u >> 1;
            float c = cs[t], sn = cs[32 + t];
            float xr = qs[h * QKD + DN + 2 * t], xi = qs[h * QKD + DN + 2 * t + 1];
            val = (u & 1) ? (xr * sn + xi * c) : (xr * c - xi * sn);
        }
        Qb[((size_t)h * S + s) * QKD + d] = tf32r(val);
    }
}

// ---------------- build K/V: rot part computed once (shared across heads) ----------------
__global__ void build_kv2(const float* __restrict__ kv, const float* __restrict__ qackv,
                          const float* __restrict__ freqs,
                          float* __restrict__ Kb, float* __restrict__ Vb) {
    const int s = blockIdx.x;
    __shared__ float rot[DR];
    if (threadIdx.x < DR / 2) {
        float f = freqs[s * (DR / 2) + threadIdx.x];
        float c = cosf(f), sn = sinf(f);
        const float* kr = qackv + (size_t)s * W1N + (RQ + RKV);
        float xr = kr[2 * threadIdx.x], xi = kr[2 * threadIdx.x + 1];
        rot[2 * threadIdx.x]     = tf32r(xr * c - xi * sn);
        rot[2 * threadIdx.x + 1] = tf32r(xr * sn + xi * c);
    }
    __syncthreads();
    const float* kvs = kv + (size_t)s * (NH * (DN + DV));
    const int PER = DN + DV + DR;    // 320 outputs per head
    for (int idx = threadIdx.x; idx < NH * PER; idx += 256) {
        int h = idx / PER, d = idx - h * PER;
        if (d < DN) {
            Kb[((size_t)h * S + s) * QKD + d] = tf32r(kvs[h * (DN + DV) + d]);
        } else if (d < QKD) {
            Kb[((size_t)h * S + s) * QKD + d] = rot[d - DN];
        } else {
            int dv = d - QKD;
            Vb[((size_t)h * S + s) * DV + dv] = tf32r(kvs[h * (DN + DV) + DN + dv]);
        }
    }
}

// ---------------- host ----------------
static float* sym_addr(const void* symbol) {
    void* p = nullptr;
    cudaGetSymbolAddress(&p, symbol);
    return (float*)p;
}

static void launch_round(const float* src, float* dst, size_t n) {
    int n4 = (int)(n / 4);
    round_tf32_kernel<<<(n4 + 255) / 256, 256>>>((const float4*)src, (float4*)dst, n4);
}

static void launch_gemm(const float* A, const float* B, float* C, int M, int N, int K) {
    dim3 grid((N + BN - 1) / BN, M / BM);
    gemm_nt_big<<<grid, 256, GEMM_SMEM>>>(A, B, C, M, N, K);
}

extern "C" void kernel_launch(void* const* d_in, const int* in_sizes, int n_in,
                              void* d_out, int out_size) {
    const float* hidden    = (const float*)d_in[0];
    const float* freqs     = (const float*)d_in[1];
    const float* q_a_w     = (const float*)d_in[2];
    const float* q_a_ln_w  = (const float*)d_in[3];
    const float* q_b_w     = (const float*)d_in[4];
    const float* kv_a_w    = (const float*)d_in[5];
    const float* kv_a_ln_w = (const float*)d_in[6];
    const float* kv_b_w    = (const float*)d_in[7];
    const float* o_w       = (const float*)d_in[8];
    float* out = (float*)d_out;

    float* qackv = sym_addr(g_qackv);
    float* qan  = sym_addr(g_qan);
    float* q    = sym_addr(g_q);
    float* ckvn = sym_addr(g_ckvn);
    float* kv   = sym_addr(g_kv);
    float* Qb   = sym_addr(g_Q);
    float* Kb   = sym_addr(g_K);
    float* Vb   = sym_addr(g_V);
    float* attn = sym_addr(g_attn);
    float* hid  = sym_addr(g_hid);
    float* w1   = sym_addr(g_w1);
    float* qbw  = sym_addr(g_qbw);
    float* kvbw = sym_addr(g_kvbw);
    float* ow   = sym_addr(g_ow);

    cudaFuncSetAttribute(flash_attn, cudaFuncAttributeMaxDynamicSharedMemorySize, FLASH_SMEM);
    cudaFuncSetAttribute(gemm_nt_big, cudaFuncAttributeMaxDynamicSharedMemorySize, GEMM_SMEM);

    // 0) pre-round inputs to tf32 (rna), once per call
    launch_round(hidden, hid,  (size_t)S * Hh);
    launch_round(q_a_w,  w1,                    (size_t)RQ * Hh);    // rows 0..1535
    launch_round(kv_a_w, w1 + (size_t)RQ * Hh,  (size_t)CKVW * Hh);  // rows 1536..2111
    launch_round(q_b_w,  qbw,  (size_t)NH * QKD * RQ);
    launch_round(kv_b_w, kvbw, (size_t)NH * (DN + DV) * RKV);
    launch_round(o_w,    ow,   (size_t)Hh * Hh);

    // 1) [q_a | ckv] = hid @ w1^T   [2048, 2112]  (merged G1+G4, one full wave)
    launch_gemm(hid, w1, qackv, S, W1N, Hh);
    // 2) rmsnorm(q_a) -> tf32
    rmsnorm_kernel<<<S, 256>>>(qackv, q_a_ln_w, qan, RQ, W1N, RQ);
    // 3) q = qan @ qbw^T            [2048,6144]
    launch_gemm(qan, qbw, q, S, NH * QKD, RQ);
    // 5) rmsnorm(ckv[:, :512]) -> tf32
    rmsnorm_kernel<<<S, 256>>>(qackv + RQ, kv_a_ln_w, ckvn, RKV, W1N, RKV);
    // 6) kv = ckvn @ kvbw^T         [2048,8192]
    launch_gemm(ckvn, kvbw, kv, S, NH * (DN + DV), RKV);
    // 7) assemble Q with RoPE (tf32)
    build_q2<<<S, 256>>>(q, freqs, Qb);
    // 8) assemble K (RoPE, shared rot) and V (tf32)
    build_kv2<<<S, 256>>>(kv, qackv, freqs, Kb, Vb);
    // 9-11) fused flash attention -> g_attn (tf32-rounded)
    flash_attn<<<dim3(S / 128, NH), 256, FLASH_SMEM>>>(Qb, Kb, Vb, attn);
    // 12) out = attn @ ow^T         [2048,4096]
    launch_gemm(attn, ow, out, S, Hh, Hh);
}

// round 15
// speedup vs baseline: 1.8502x; 1.5987x over previous
#include <cuda_runtime.h>
#include <cuda_fp16.h>
#include <math.h>
#include <cstdint>
#include <cstddef>

// ---------------- problem constants ----------------
#define S    2048
#define Hh   4096
#define NH   32
#define DN   128
#define DR   64
#define DV   128
#define QKD  192          // DN + DR
#define RQ   1536
#define RKV  512
#define CKVW 576          // RKV + DR
#define W1N  (RQ + CKVW)  // 2112

#define SM_SCALE 0.072168783648703220563f   // 192^-0.5

// ---- fp16 GEMM tiling: 128x256x32, slab-split smem (L=16 halfs) ----
#define HBM 128
#define HBN 256
#define HBK 32
#define HSTG 4
#define A_ST_H (HBM * HBK)          // 4096 halfs per stage
#define B_ST_H (HBN * HBK)          // 8192 halfs per stage
#define STG_H  (A_ST_H + B_ST_H)    // 12288 halfs
#define GEMM_SMEM (HSTG * STG_H * 2)   // 98304 B

// ---------------- scratch (device globals; allocation-free) ----------------
__device__ float  g_qackv[S * W1N];            // [q_a | ckv] f32
__device__ __half g_qan [S * RQ];
__device__ float  g_q   [S * NH * QKD];
__device__ __half g_ckvn[S * RKV];
__device__ float  g_kv  [S * NH * (DN+DV)];
__device__ __half g_Q   [(size_t)NH * S * QKD];
__device__ __half g_K   [(size_t)NH * S * QKD];
__device__ __half g_Vt  [(size_t)NH * DV * S]; // transposed: [h][d][s]
__device__ __half g_attn[S * Hh];
// fp16 copies of inputs
__device__ __half g_hid [S * Hh];
__device__ __half g_w1  [(size_t)W1N * Hh];
__device__ __half g_qbw [NH * QKD * RQ];
__device__ __half g_kvbw[NH * (DN+DV) * RKV];
__device__ __half g_ow  [(size_t)Hh * Hh];

// ---------------- helpers ----------------
__device__ __forceinline__ void cp_async16(void* smem, const void* gmem, bool pred) {
    unsigned int s = (unsigned int)__cvta_generic_to_shared(smem);
    int sz = pred ? 16 : 0;
    asm volatile("cp.async.cg.shared.global [%0], [%1], 16, %2;\n" :: "r"(s), "l"(gmem), "r"(sz));
}
__device__ __forceinline__ void cp_async_commit() { asm volatile("cp.async.commit_group;\n"); }
template<int N_> __device__ __forceinline__ void cp_async_wait() { asm volatile("cp.async.wait_group %0;\n" :: "n"(N_)); }

__device__ __forceinline__ uint32_t pack2h(float a, float b) {
    __half2 h = __floats2half2_rn(a, b);
    return *reinterpret_cast<uint32_t*>(&h);
}
// m16n8k16 fp16 MMA, f32 accumulate. A row-major, B col-major.
__device__ __forceinline__ void mma_f16(float* c, const uint32_t* a, uint32_t b0, uint32_t b1) {
    asm("mma.sync.aligned.m16n8k16.row.col.f32.f16.f16.f32 "
        "{%0,%1,%2,%3},{%4,%5,%6,%7},{%8,%9},{%0,%1,%2,%3};"
        : "+f"(c[0]), "+f"(c[1]), "+f"(c[2]), "+f"(c[3])
        : "r"(a[0]), "r"(a[1]), "r"(a[2]), "r"(a[3]), "r"(b0), "r"(b1));
}

// ---------------- f32 -> f16 conversion (vectorized) ----------------
__global__ void to_half_kernel(const float4* __restrict__ in, uint2* __restrict__ out, int n4) {
    int i = blockIdx.x * blockDim.x + threadIdx.x;
    if (i < n4) {
        float4 v = in[i];
        uint2 o;
        o.x = pack2h(v.x, v.y);
        o.y = pack2h(v.z, v.w);
        out[i] = o;
    }
}

// ============ fp16 NT GEMM: C[M,N] = A[M,K] * B[N,K]^T, f32 out ============
// 8 warps 2(M)x4(N), warp tile 64x64. Slab-split smem: per stage 2 slabs of 16 k.
// k-permuted fragment slots: thread t holds k = {4t..4t+3} -> all uint2 loads.
__global__ __launch_bounds__(256, 1)
void gemm_h(const __half* __restrict__ A, const __half* __restrict__ B,
            float* __restrict__ C, int M, int N, int K) {
    extern __shared__ __half smh[];
    const int tid  = threadIdx.x;
    const int warp = tid >> 5, lane = tid & 31;
    const int g    = lane >> 2, t = lane & 3;
    const int wm   = warp >> 2, wn = warp & 3;
    const int bm   = blockIdx.y * HBM, bn = blockIdx.x * HBN;

    float c[4][8][4];
#pragma unroll
    for (int i = 0; i < 4; i++)
#pragma unroll
        for (int j = 0; j < 8; j++) { c[i][j][0] = c[i][j][1] = c[i][j][2] = c[i][j][3] = 0.f; }

    const int T = K / HBK;

    auto load_stage = [&](int kt, int stg) {
        __half* base = smh + stg * STG_H;
        const int k0 = kt * HBK;
        // A: 128 rows x 2 slabs x 2 chunks = 512 chunks (2/thread)
#pragma unroll
        for (int u = 0; u < 2; u++) {
            int f = tid + u * 256;
            int row = f >> 2, rem = f & 3;
            int slab = rem >> 1, c8 = (rem & 1) * 8;
            cp_async16(base + slab * 2048 + row * 16 + c8,
                       A + (size_t)(bm + row) * K + k0 + slab * 16 + c8, true);
        }
        // B: 256 rows x 2 slabs x 2 chunks = 1024 chunks (4/thread)
#pragma unroll
        for (int u = 0; u < 4; u++) {
            int f = tid + u * 256;
            int row = f >> 2, rem = f & 3;
            int slab = rem >> 1, c8 = (rem & 1) * 8;
            bool p = (bn + row) < N;
            cp_async16(base + A_ST_H + slab * 4096 + row * 16 + c8,
                       B + (size_t)(p ? (bn + row) : 0) * K + k0 + slab * 16 + c8, p);
        }
        cp_async_commit();
    };

#pragma unroll
    for (int s = 0; s < HSTG - 1; s++) {
        if (s < T) load_stage(s, s); else cp_async_commit();
    }

    for (int kt = 0; kt < T; kt++) {
        cp_async_wait<HSTG - 2>();
        __syncthreads();
        if (kt + HSTG - 1 < T) load_stage(kt + HSTG - 1, (kt + HSTG - 1) % HSTG);
        else cp_async_commit();

        const __half* base = smh + (kt % HSTG) * STG_H;
#pragma unroll
        for (int s = 0; s < 2; s++) {
            const __half* As = base + s * 2048;
            const __half* Bs = base + A_ST_H + s * 4096;
            uint32_t a[4][4];
#pragma unroll
            for (int i = 0; i < 4; i++) {
                const int rb = wm * 64 + i * 16;
                uint2 v0 = *(const uint2*)(As + (rb + g) * 16 + 4 * t);
                uint2 v1 = *(const uint2*)(As + (rb + g + 8) * 16 + 4 * t);
                a[i][0] = v0.x; a[i][1] = v1.x; a[i][2] = v0.y; a[i][3] = v1.y;
            }
            uint32_t bf[8][2];
#pragma unroll
            for (int j = 0; j < 8; j++) {
                const int nb = wn * 64 + j * 8;
                uint2 vb = *(const uint2*)(Bs + (nb + g) * 16 + 4 * t);
                bf[j][0] = vb.x; bf[j][1] = vb.y;
            }
#pragma unroll
            for (int i = 0; i < 4; i++)
#pragma unroll
                for (int j = 0; j < 8; j++)
                    mma_f16(c[i][j], a[i], bf[j][0], bf[j][1]);
        }
        __syncthreads();
    }

#pragma unroll
    for (int i = 0; i < 4; i++) {
        const int gm0 = bm + wm * 64 + i * 16 + g;
        const int gm1 = gm0 + 8;
#pragma unroll
        for (int j = 0; j < 8; j++) {
            const int gn = bn + wn * 64 + j * 8 + 2 * t;
            if (gn < N) {
                float2 v0; v0.x = c[i][j][0]; v0.y = c[i][j][1];
                float2 v1; v1.x = c[i][j][2]; v1.y = c[i][j][3];
                *(float2*)&C[(size_t)gm0 * N + gn] = v0;
                *(float2*)&C[(size_t)gm1 * N + gn] = v1;
            }
        }
    }
}

// ================== fused flash attention (fp16 mma.sync) ==================
// smem (halfs): K 2 bufs x 12 slabs x 64 x 16 = 24576; Vt 2 x 4 slabs x 128 x 16 = 16384;
// P 8 warps x 16 x 80 = 10240. Total 51200 halfs = 102400 B.
#define KSH 12288
#define VSH 8192
#define PS_LDH 80
#define PSH (16 * PS_LDH)
#define FLASH_SMEM ((2 * KSH + 2 * VSH + 8 * PSH) * 2)

__global__ __launch_bounds__(256, 1)
void flash_attn(const __half* __restrict__ Qb, const __half* __restrict__ Kb,
                const __half* __restrict__ Vtb, __half* __restrict__ Out) {
    extern __shared__ __half smh[];
    __half* KsB = smh;
    __half* VsB = smh + 2 * KSH;
    __half* PsB = smh + 2 * KSH + 2 * VSH;

    const int qt   = (int)(gridDim.x - 1 - blockIdx.x);  // heavy tiles first
    const int h    = blockIdx.y;
    const int bm   = qt * 128;
    const int tid  = threadIdx.x;
    const int warp = tid >> 5, lane = tid & 31;
    const int g    = lane >> 2, t = lane & 3;
    const int row0 = bm + warp * 16 + g;
    const int row1 = row0 + 8;

    const __half* Qh  = Qb  + (size_t)h * S * QKD;
    const __half* Kh  = Kb  + (size_t)h * S * QKD;
    const __half* Vth = Vtb + (size_t)h * DV * S;
    __half* Pw = PsB + warp * PSH;

    // ---- preload Q fragments: 12 kgroups of 16, k-permuted {4t..4t+3} ----
    uint32_t qa[12][4];
    {
        const __half* q0 = Qh + (size_t)row0 * QKD;
        const __half* q1 = Qh + (size_t)row1 * QKD;
#pragma unroll
        for (int kg = 0; kg < 12; kg++) {
            uint2 w0 = *(const uint2*)(q0 + 16 * kg + 4 * t);
            uint2 w1 = *(const uint2*)(q1 + 16 * kg + 4 * t);
            qa[kg][0] = w0.x; qa[kg][1] = w1.x; qa[kg][2] = w0.y; qa[kg][3] = w1.y;
        }
    }

    float o[16][4];
#pragma unroll
    for (int i = 0; i < 16; i++) { o[i][0] = o[i][1] = o[i][2] = o[i][3] = 0.f; }
    float m0 = -1e30f, m1 = -1e30f, l0 = 0.f, l1 = 0.f;

    const int NT = 2 * qt + 2;

    auto load_kv = [&](int jtile, int buf) {
        // K: 64 rows x 12 slabs x 2 chunks = 1536 chunks (6/thread)
        __half* kdst = KsB + buf * KSH;
        const __half* ksrc = Kh + (size_t)(64 * jtile) * QKD;
#pragma unroll
        for (int i = 0; i < 6; i++) {
            int f = tid + i * 256;
            int row = f / 24, rem = f % 24;
            int slab = rem >> 1, c8 = (rem & 1) * 8;
            cp_async16(kdst + slab * 1024 + row * 16 + c8,
                       ksrc + (size_t)row * QKD + slab * 16 + c8, true);
        }
        // Vt: 128 rows(d) x 4 slabs(j) x 2 chunks = 1024 chunks (4/thread)
        __half* vdst = VsB + buf * VSH;
        const __half* vsrc = Vth;   // [d][s]
#pragma unroll
        for (int i = 0; i < 4; i++) {
            int f = tid + i * 256;
            int row = f >> 3, rem = f & 7;
            int slab = rem >> 1, c8 = (rem & 1) * 8;
            cp_async16(vdst + slab * 2048 + row * 16 + c8,
                       vsrc + (size_t)row * S + 64 * jtile + slab * 16 + c8, true);
        }
        cp_async_commit();
    };

    load_kv(0, 0);
    cp_async_commit();   // keep group parity with loop's expectations

    for (int jt = 0; jt < NT; jt++) {
        const int buf = jt & 1;
        __syncthreads();
        if (jt + 1 < NT) { load_kv(jt + 1, buf ^ 1); cp_async_wait<1>(); }
        else             { cp_async_wait<0>(); }
        __syncthreads();

        const __half* Kst = KsB + buf * KSH;
        const __half* Vst = VsB + buf * VSH;

        // ---- S = Q K^T: 8 n-blocks x 12 kgroups ----
        float sc[8][4];
#pragma unroll
        for (int njp = 0; njp < 4; njp++) {
            float s0[4] = {0.f, 0.f, 0.f, 0.f};
            float s1[4] = {0.f, 0.f, 0.f, 0.f};
            const int kr0 = ((2 * njp) * 8 + g) * 16 + 4 * t;
            const int kr1 = ((2 * njp + 1) * 8 + g) * 16 + 4 * t;
#pragma unroll
            for (int kg = 0; kg < 12; kg++) {
                uint2 vb0 = *(const uint2*)(Kst + kg * 1024 + kr0);
                mma_f16(s0, qa[kg], vb0.x, vb0.y);
                uint2 vb1 = *(const uint2*)(Kst + kg * 1024 + kr1);
                mma_f16(s1, qa[kg], vb1.x, vb1.y);
            }
#pragma unroll
            for (int e = 0; e < 4; e++) { sc[2 * njp][e] = s0[e]; sc[2 * njp + 1][e] = s1[e]; }
        }

        // ---- causal mask ----
#pragma unroll
        for (int nj = 0; nj < 8; nj++) {
            int colb = 64 * jt + 8 * nj + 2 * t;
            if (colb     > row0) sc[nj][0] = -1e30f;
            if (colb + 1 > row0) sc[nj][1] = -1e30f;
            if (colb     > row1) sc[nj][2] = -1e30f;
            if (colb + 1 > row1) sc[nj][3] = -1e30f;
        }

        // ---- online softmax ----
        float tm0 = -1e30f, tm1 = -1e30f;
#pragma unroll
        for (int nj = 0; nj < 8; nj++) {
            tm0 = fmaxf(tm0, fmaxf(sc[nj][0], sc[nj][1]));
            tm1 = fmaxf(tm1, fmaxf(sc[nj][2], sc[nj][3]));
        }
        tm0 = fmaxf(tm0, __shfl_xor_sync(0xffffffffu, tm0, 1));
        tm0 = fmaxf(tm0, __shfl_xor_sync(0xffffffffu, tm0, 2));
        tm1 = fmaxf(tm1, __shfl_xor_sync(0xffffffffu, tm1, 1));
        tm1 = fmaxf(tm1, __shfl_xor_sync(0xffffffffu, tm1, 2));
        const float nm0 = fmaxf(m0, tm0), nm1 = fmaxf(m1, tm1);
        const float al0 = expf((m0 - nm0) * SM_SCALE);
        const float al1 = expf((m1 - nm1) * SM_SCALE);

        float rs0 = 0.f, rs1 = 0.f;
#pragma unroll
        for (int nj = 0; nj < 8; nj++) {
            float p0 = expf((sc[nj][0] - nm0) * SM_SCALE);
            float p1 = expf((sc[nj][1] - nm0) * SM_SCALE);
            float p2 = expf((sc[nj][2] - nm1) * SM_SCALE);
            float p3 = expf((sc[nj][3] - nm1) * SM_SCALE);
            rs0 += p0 + p1;
            rs1 += p2 + p3;
            *(uint32_t*)(Pw + g * PS_LDH + 8 * nj + 2 * t)       = pack2h(p0, p1);
            *(uint32_t*)(Pw + (g + 8) * PS_LDH + 8 * nj + 2 * t) = pack2h(p2, p3);
        }
        l0 = l0 * al0 + rs0;   // per-thread partial; quad-reduced at the end
        l1 = l1 * al1 + rs1;
        m0 = nm0; m1 = nm1;
#pragma unroll
        for (int dj = 0; dj < 16; dj++) {
            o[dj][0] *= al0; o[dj][1] *= al0;
            o[dj][2] *= al1; o[dj][3] *= al1;
        }
        __syncwarp();

        // ---- O += P V: 4 kgroups x 16 n-blocks ----
#pragma unroll
        for (int kg = 0; kg < 4; kg++) {
            uint32_t pa[4];
            uint2 pw0 = *(const uint2*)(Pw + g * PS_LDH + 16 * kg + 4 * t);
            uint2 pw1 = *(const uint2*)(Pw + (g + 8) * PS_LDH + 16 * kg + 4 * t);
            pa[0] = pw0.x; pa[1] = pw1.x; pa[2] = pw0.y; pa[3] = pw1.y;
            const __half* vs = Vst + kg * 2048;
#pragma unroll
            for (int dj = 0; dj < 16; dj += 2) {
                uint2 vb0 = *(const uint2*)(vs + (8 * dj + g) * 16 + 4 * t);
                mma_f16(o[dj], pa, vb0.x, vb0.y);
                uint2 vb1 = *(const uint2*)(vs + (8 * (dj + 1) + g) * 16 + 4 * t);
                mma_f16(o[dj + 1], pa, vb1.x, vb1.y);
            }
        }
        __syncwarp();
    }

    // quad reduction of softmax denominator
    l0 += __shfl_xor_sync(0xffffffffu, l0, 1);
    l0 += __shfl_xor_sync(0xffffffffu, l0, 2);
    l1 += __shfl_xor_sync(0xffffffffu, l1, 1);
    l1 += __shfl_xor_sync(0xffffffffu, l1, 2);

    const float inv0 = 1.f / l0, inv1 = 1.f / l1;
    __half* or0 = Out + (size_t)row0 * Hh + h * DV;
    __half* or1 = Out + (size_t)row1 * Hh + h * DV;
#pragma unroll
    for (int dj = 0; dj < 16; dj++) {
        *(uint32_t*)(or0 + 8 * dj + 2 * t) = pack2h(o[dj][0] * inv0, o[dj][1] * inv0);
        *(uint32_t*)(or1 + 8 * dj + 2 * t) = pack2h(o[dj][2] * inv1, o[dj][3] * inv1);
    }
}

// ---------------- rmsnorm over first K cols; half output ----------------
__global__ void rmsnorm_kernel(const float* __restrict__ X, const float* __restrict__ w,
                               __half* __restrict__ Y, int K, int ldx, int ldy) {
    const int row = blockIdx.x;
    const float* x = X + (size_t)row * ldx;
    __half* y = Y + (size_t)row * ldy;
    float ss = 0.f;
    for (int j = threadIdx.x; j < K; j += blockDim.x) { float v = x[j]; ss += v * v; }
    __shared__ float red[256];
    red[threadIdx.x] = ss;
    __syncthreads();
    for (int s = 128; s > 0; s >>= 1) {
        if (threadIdx.x < s) red[threadIdx.x] += red[threadIdx.x + s];
        __syncthreads();
    }
    float inv = rsqrtf(red[0] / (float)K + 1e-6f);
    for (int j = threadIdx.x; j < K; j += blockDim.x)
        y[j] = __float2half_rn(x[j] * inv * w[j]);
}

// ---------------- build Q (RoPE), half output ----------------
__global__ void build_q2(const float* __restrict__ q, const float* __restrict__ freqs,
                         __half* __restrict__ Qb) {
    const int s = blockIdx.x;
    __shared__ float cs[DR];
    if (threadIdx.x < DR / 2) {
        float f = freqs[s * (DR / 2) + threadIdx.x];
        cs[threadIdx.x]      = cosf(f);
        cs[32 + threadIdx.x] = sinf(f);
    }
    __syncthreads();
    const float* qs = q + (size_t)s * (NH * QKD);
    for (int idx = threadIdx.x; idx < NH * QKD; idx += 256) {
        int h = idx / QKD, d = idx - h * QKD;
        float val;
        if (d < DN) {
            val = qs[h * QKD + d];
        } else {
            int u = d - DN, t = u >> 1;
            float c = cs[t], sn = cs[32 + t];
            float xr = qs[h * QKD + DN + 2 * t], xi = qs[h * QKD + DN + 2 * t + 1];
            val = (u & 1) ? (xr * sn + xi * c) : (xr * c - xi * sn);
        }
        Qb[((size_t)h * S + s) * QKD + d] = __float2half_rn(val);
    }
}

// ---------------- build K (RoPE, shared rot), half output ----------------
__global__ void build_k2(const float* __restrict__ kv, const float* __restrict__ qackv,
                         const float* __restrict__ freqs, __half* __restrict__ Kb) {
    const int s = blockIdx.x;
    __shared__ __half rot[DR];
    if (threadIdx.x < DR / 2) {
        float f = freqs[s * (DR / 2) + threadIdx.x];
        float c = cosf(f), sn = sinf(f);
        const float* kr = qackv + (size_t)s * W1N + (RQ + RKV);
        float xr = kr[2 * threadIdx.x], xi = kr[2 * threadIdx.x + 1];
        rot[2 * threadIdx.x]     = __float2half_rn(xr * c - xi * sn);
        rot[2 * threadIdx.x + 1] = __float2half_rn(xr * sn + xi * c);
    }
    __syncthreads();
    const float* kvs = kv + (size_t)s * (NH * (DN + DV));
    for (int idx = threadIdx.x; idx < NH * QKD; idx += 256) {
        int h = idx / QKD, d = idx - h * QKD;
        if (d < DN) {
            Kb[((size_t)h * S + s) * QKD + d] = __float2half_rn(kvs[h * (DN + DV) + d]);
        } else {
            Kb[((size_t)h * S + s) * QKD + d] = rot[d - DN];
        }
    }
}

// ---------------- V transpose: kv f32 [s][h][DN+d] -> Vt half [h][d][s] ----------------
__global__ void vtrans(const float* __restrict__ kv, __half* __restrict__ Vt) {
    const int h = blockIdx.x, d0 = blockIdx.y * 32, s0 = blockIdx.z * 64;
    __shared__ __half tile[32][65];
    const int dl = threadIdx.x & 31, sl = threadIdx.x >> 5;   // 32 d x 8 s
    for (int ss = sl; ss < 64; ss += 8)
        tile[dl][ss] = __float2half_rn(
            kv[(size_t)(s0 + ss) * (NH * (DN + DV)) + h * (DN + DV) + DN + d0 + dl]);
    __syncthreads();
    const int sl2 = threadIdx.x & 63, dl2 = threadIdx.x >> 6; // 64 s x 4 d
    for (int dd = dl2; dd < 32; dd += 4)
        Vt[((size_t)h * DV + d0 + dd) * S + s0 + sl2] = tile[dd][sl2];
}

// ---------------- host ----------------
static void* sym_addr(const void* symbol) {
    void* p = nullptr;
    cudaGetSymbolAddress(&p, symbol);
    return p;
}

static void launch_half(const float* src, __half* dst, size_t n) {
    int n4 = (int)(n / 4);
    to_half_kernel<<<(n4 + 255) / 256, 256>>>((const float4*)src, (uint2*)dst, n4);
}

static void launch_gemm(const __half* A, const __half* B, float* C, int M, int N, int K) {
    dim3 grid((N + HBN - 1) / HBN, M / HBM);
    gemm_h<<<grid, 256, GEMM_SMEM>>>(A, B, C, M, N, K);
}

extern "C" void kernel_launch(void* const* d_in, const int* in_sizes, int n_in,
                              void* d_out, int out_size) {
    const float* hidden    = (const float*)d_in[0];
    const float* freqs     = (const float*)d_in[1];
    const float* q_a_w     = (const float*)d_in[2];
    const float* q_a_ln_w  = (const float*)d_in[3];
    const float* q_b_w     = (const float*)d_in[4];
    const float* kv_a_w    = (const float*)d_in[5];
    const float* kv_a_ln_w = (const float*)d_in[6];
    const float* kv_b_w    = (const float*)d_in[7];
    const float* o_w       = (const float*)d_in[8];
    float* out = (float*)d_out;

    float*  qackv = (float*) sym_addr(g_qackv);
    __half* qan   = (__half*)sym_addr(g_qan);
    float*  q     = (float*) sym_addr(g_q);
    __half* ckvn  = (__half*)sym_addr(g_ckvn);
    float*  kv    = (float*) sym_addr(g_kv);
    __half* Qb    = (__half*)sym_addr(g_Q);
    __half* Kb    = (__half*)sym_addr(g_K);
    __half* Vt    = (__half*)sym_addr(g_Vt);
    __half* attn  = (__half*)sym_addr(g_attn);
    __half* hid   = (__half*)sym_addr(g_hid);
    __half* w1    = (__half*)sym_addr(g_w1);
    __half* qbw   = (__half*)sym_addr(g_qbw);
    __half* kvbw  = (__half*)sym_addr(g_kvbw);
    __half* ow    = (__half*)sym_addr(g_ow);

    cudaFuncSetAttribute(flash_attn, cudaFuncAttributeMaxDynamicSharedMemorySize, FLASH_SMEM);
    cudaFuncSetAttribute(gemm_h, cudaFuncAttributeMaxDynamicSharedMemorySize, GEMM_SMEM);

    // 0) convert inputs to fp16 once per call
    launch_half(hidden, hid,  (size_t)S * Hh);
    launch_half(q_a_w,  w1,                    (size_t)RQ * Hh);
    launch_half(kv_a_w, w1 + (size_t)RQ * Hh,  (size_t)CKVW * Hh);
    launch_half(q_b_w,  qbw,  (size_t)NH * QKD * RQ);
    launch_half(kv_b_w, kvbw, (size_t)NH * (DN + DV) * RKV);
    launch_half(o_w,    ow,   (size_t)Hh * Hh);

    // 1) [q_a | ckv] = hid @ w1^T   [2048, 2112] (merged)
    launch_gemm(hid, w1, qackv, S, W1N, Hh);
    // 2) rmsnorm(q_a) -> half
    rmsnorm_kernel<<<S, 256>>>(qackv, q_a_ln_w, qan, RQ, W1N, RQ);
    // 3) q = qan @ qbw^T            [2048,6144]
    launch_gemm(qan, qbw, q, S, NH * QKD, RQ);
    // 5) rmsnorm(ckv[:, :512]) -> half
    rmsnorm_kernel<<<S, 256>>>(qackv + RQ, kv_a_ln_w, ckvn, RKV, W1N, RKV);
    // 6) kv = ckvn @ kvbw^T         [2048,8192]
    launch_gemm(ckvn, kvbw, kv, S, NH * (DN + DV), RKV);
    // 7) assemble Q with RoPE (half)
    build_q2<<<S, 256>>>(q, freqs, Qb);
    // 8) assemble K (half); V transposed [h][d][s]
    build_k2<<<S, 256>>>(kv, qackv, freqs, Kb);
    vtrans<<<dim3(NH, DV / 32, S / 64), 256>>>(kv, Vt);
    // 9-11) fused flash attention -> attn (half)
    flash_attn<<<dim3(S / 128, NH), 256, FLASH_SMEM>>>(Qb, Kb, Vt, attn);
    // 12) out = attn @ ow^T         [2048,4096]
    launch_gemm(attn, ow, out, S, Hh, Hh);
}